// round 1
// baseline (speedup 1.0000x reference)
#include <cuda_runtime.h>
#include <cstdint>

// Problem constants
#define BATCH 32
#define CDIM  64
#define HW    4096              // 64*64
#define NPTS  (BATCH * HW)      // 131072
#define KCODES 1024
#define ZQ_ELEMS (NPTS * CDIM)  // 8388608

// Scratch (device globals: allocation-free rule)
__device__ float  g_znorm[NPTS];
__device__ float  g_enorm[KCODES];
__device__ int    g_idx[NPTS];
__device__ double g_part[1024];

// ---------------------------------------------------------------------------
// Packed fp32x2 helpers (sm_103a: 2x fp32 FMA throughput, PTX-only)
// ---------------------------------------------------------------------------
__device__ __forceinline__ void fma2(unsigned long long& d,
                                     unsigned long long a,
                                     unsigned long long b) {
    asm("fma.rn.f32x2 %0, %1, %2, %0;" : "+l"(d) : "l"(a), "l"(b));
}
__device__ __forceinline__ unsigned long long dup_f32(float x) {
    unsigned long long r;
    unsigned int xi = __float_as_uint(x);
    asm("mov.b64 %0, {%1, %1};" : "=l"(r) : "r"(xi));
    return r;
}
__device__ __forceinline__ float lo_f32(unsigned long long v) {
    return __uint_as_float((unsigned int)(v & 0xFFFFFFFFull));
}
__device__ __forceinline__ float hi_f32(unsigned long long v) {
    return __uint_as_float((unsigned int)(v >> 32));
}

// ---------------------------------------------------------------------------
// Kernel 0a: per-point ||z||^2 (sequential fp32 sum over C, matching jnp.sum)
// ---------------------------------------------------------------------------
__global__ void znorm_kernel(const float* __restrict__ z) {
    int n = blockIdx.x * blockDim.x + threadIdx.x;   // 0..NPTS-1
    int b  = n >> 12;
    int hw = n & 4095;
    const float* p = z + (size_t)b * (CDIM * HW) + hw;
    float acc = 0.0f;
#pragma unroll
    for (int c = 0; c < CDIM; ++c) {
        float v = p[(size_t)c * HW];
        acc = __fadd_rn(acc, __fmul_rn(v, v));
    }
    g_znorm[n] = acc;
}

// ---------------------------------------------------------------------------
// Kernel 0b: per-code ||e||^2
// ---------------------------------------------------------------------------
__global__ void enorm_kernel(const float* __restrict__ emb) {
    int k = blockIdx.x * blockDim.x + threadIdx.x;   // 0..1023
    const float* p = emb + (size_t)k * CDIM;
    float acc = 0.0f;
#pragma unroll
    for (int c = 0; c < CDIM; ++c) {
        float v = p[c];
        acc = __fadd_rn(acc, __fmul_rn(v, v));
    }
    g_enorm[k] = acc;
}

// ---------------------------------------------------------------------------
// Kernel 1: fused distance-GEMM + argmin.
//   Block tile: 64 points x 128 codes per chunk, 8 chunks covering K=1024.
//   Thread tile: 4 points x 8 codes (4 f32x2 code-pairs) -> 16 fma.f32x2/iter.
//   d_k = fl( fl(znorm + enorm_k) - fl(2 * dot) ), argmin w/ lowest-k ties
//   via packed u64 key = (d_bits << 32) | k.
// ---------------------------------------------------------------------------
#define ESTRIDE 132  // 128 + 4 pad (floats per smem row)

__global__ __launch_bounds__(256) void argmin_kernel(
    const float* __restrict__ z, const float* __restrict__ emb) {
    __shared__ float e_s[CDIM * ESTRIDE];   // [c][k'] transposed, swizzled

    const int tid = threadIdx.x;
    const int tx = tid & 15;        // code group (16 x 8 codes = 128)
    const int ty = tid >> 4;        // point group (16 x 4 points = 64)

    const int m0  = blockIdx.x * 64;          // first point of block
    const int b   = m0 >> 12;
    const int hw0 = m0 & 4095;
    const float* zp = z + (size_t)b * (CDIM * HW) + hw0 + (ty << 2);

    // znorm for this thread's 4 points
    const float4 zn4 = *(const float4*)&g_znorm[m0 + (ty << 2)];
    const float znA[4] = {zn4.x, zn4.y, zn4.z, zn4.w};

    unsigned long long key[4];
#pragma unroll
    for (int i = 0; i < 4; ++i) key[i] = 0xFFFFFFFFFFFFFFFFull;

    for (int chunk = 0; chunk < 8; ++chunk) {
        const int kb = chunk << 7;   // 128 codes per chunk

        __syncthreads();
        // Cooperative transpose-load of emb chunk into e_s[c][k'^sig]
        {
            const int cg = tid & 15;        // c-group (4 floats)
            const int kk0 = tid >> 4;       // row within pass
            const int sig = (cg & 3) << 3;  // XOR swizzle on k' bits 3-4
#pragma unroll
            for (int p = 0; p < 8; ++p) {
                const int kk = (p << 4) + kk0;           // 0..127
                const float4 v = *(const float4*)&emb[(size_t)(kb + kk) * CDIM + (cg << 2)];
                const int col = kk ^ sig;
                e_s[((cg << 2) + 0) * ESTRIDE + col] = v.x;
                e_s[((cg << 2) + 1) * ESTRIDE + col] = v.y;
                e_s[((cg << 2) + 2) * ESTRIDE + col] = v.z;
                e_s[((cg << 2) + 3) * ESTRIDE + col] = v.w;
            }
        }
        __syncthreads();

        unsigned long long acc[16];
#pragma unroll
        for (int i = 0; i < 16; ++i) acc[i] = 0ull;

#pragma unroll 16
        for (int c = 0; c < CDIM; ++c) {
            const float4 zv = *(const float4*)(zp + (size_t)c * HW);
            unsigned long long za[4];
            za[0] = dup_f32(zv.x); za[1] = dup_f32(zv.y);
            za[2] = dup_f32(zv.z); za[3] = dup_f32(zv.w);

            const int sig = ((c >> 2) & 3) << 3;
            const int g0 = (tx << 3) ^ sig;              // 8-aligned
            const float* er = &e_s[c * ESTRIDE + g0];
            const ulonglong2 e01 = *(const ulonglong2*)er;        // codes tx*8+0..3
            const ulonglong2 e23 = *(const ulonglong2*)(er + 4);  // codes tx*8+4..7
            unsigned long long eb[4] = {e01.x, e01.y, e23.x, e23.y};

#pragma unroll
            for (int i = 0; i < 4; ++i)
#pragma unroll
                for (int n = 0; n < 4; ++n)
                    fma2(acc[i * 4 + n], za[i], eb[n]);
        }

        // Chunk epilogue: scores + running argmin
        const float4 en0 = *(const float4*)&g_enorm[kb + (tx << 3)];
        const float4 en1 = *(const float4*)&g_enorm[kb + (tx << 3) + 4];
        const float enA[8] = {en0.x, en0.y, en0.z, en0.w, en1.x, en1.y, en1.z, en1.w};
        const int kbase = kb + (tx << 3);

#pragma unroll
        for (int i = 0; i < 4; ++i) {
            const float zn = znA[i];
#pragma unroll
            for (int n = 0; n < 4; ++n) {
                const float alo = lo_f32(acc[i * 4 + n]);
                const float ahi = hi_f32(acc[i * 4 + n]);
                const float tlo = __fadd_rn(zn, enA[2 * n]);
                const float thi = __fadd_rn(zn, enA[2 * n + 1]);
                const float dlo = __fsub_rn(tlo, __fmul_rn(2.0f, alo));
                const float dhi = __fsub_rn(thi, __fmul_rn(2.0f, ahi));
                unsigned long long klo =
                    ((unsigned long long)__float_as_uint(dlo) << 32) |
                    (unsigned int)(kbase + 2 * n);
                unsigned long long khi =
                    ((unsigned long long)__float_as_uint(dhi) << 32) |
                    (unsigned int)(kbase + 2 * n + 1);
                if (klo < key[i]) key[i] = klo;
                if (khi < key[i]) key[i] = khi;
            }
        }
    }

    // Reduce over the 16 tx lanes sharing each point (xor stays within warp half)
#pragma unroll
    for (int i = 0; i < 4; ++i) {
#pragma unroll
        for (int off = 8; off >= 1; off >>= 1) {
            unsigned long long o = __shfl_xor_sync(0xFFFFFFFFu, key[i], off);
            if (o < key[i]) key[i] = o;
        }
    }
    if (tx == 0) {
#pragma unroll
        for (int i = 0; i < 4; ++i)
            g_idx[m0 + (ty << 2) + i] = (int)(key[i] & 0xFFFFFFFFull);
    }
}

// ---------------------------------------------------------------------------
// Kernel 2: gather z_q = emb[idx] into [B,C,H,W] layout + partial loss sums
// ---------------------------------------------------------------------------
__global__ __launch_bounds__(256) void gather_kernel(
    const float* __restrict__ z, const float* __restrict__ emb,
    float* __restrict__ out) {
    __shared__ int idx_s[128];
    __shared__ float es[128 * 68];
    __shared__ double red[256];

    const int tid = threadIdx.x;
    const int n0 = blockIdx.x * 128;
    const int b  = n0 >> 12;
    const int hw0 = n0 & 4095;

    if (tid < 128) idx_s[tid] = g_idx[n0 + tid];
    __syncthreads();

    // Stage 128 emb rows into smem (coalesced-by-row gather)
    {
        const int cg = tid & 15;
        const int i0 = tid >> 4;
#pragma unroll
        for (int p = 0; p < 8; ++p) {
            const int i = (p << 4) + i0;
            const float4 v = *(const float4*)&emb[(size_t)idx_s[i] * CDIM + (cg << 2)];
            *(float4*)&es[i * 68 + (cg << 2)] = v;
        }
    }
    __syncthreads();

    double acc = 0.0;
    const int m = tid & 127;
    const int chalf = tid >> 7;   // 0 or 1
#pragma unroll 8
    for (int p = 0; p < 32; ++p) {
        const int c = (p << 1) + chalf;
        const float e = es[m * 68 + c];
        const size_t off = (size_t)b * (CDIM * HW) + (size_t)c * HW + hw0 + m;
        const float zv = z[off];
        out[off] = e;
        const float d = __fsub_rn(e, zv);
        acc += (double)__fmul_rn(d, d);
    }

    red[tid] = acc;
    __syncthreads();
#pragma unroll
    for (int s = 128; s >= 1; s >>= 1) {
        if (tid < s) red[tid] += red[tid + s];
        __syncthreads();
    }
    if (tid == 0) g_part[blockIdx.x] = red[0];
}

// ---------------------------------------------------------------------------
// Kernel 3: deterministic final loss reduction.
//   loss = m + 0.5*m with m = fp32(mean((z_q - z)^2))
// ---------------------------------------------------------------------------
__global__ void loss_kernel(float* __restrict__ out, int out_size) {
    __shared__ double red[256];
    const int tid = threadIdx.x;
    double a = g_part[tid] + g_part[tid + 256] + g_part[tid + 512] + g_part[tid + 768];
    red[tid] = a;
    __syncthreads();
#pragma unroll
    for (int s = 128; s >= 1; s >>= 1) {
        if (tid < s) red[tid] += red[tid + s];
        __syncthreads();
    }
    if (tid == 0) {
        const double mean = red[0] / (double)ZQ_ELEMS;
        const float mf = (float)mean;
        out[out_size - 1] = __fadd_rn(mf, __fmul_rn(0.5f, mf));
    }
}

// ---------------------------------------------------------------------------
extern "C" void kernel_launch(void* const* d_in, const int* in_sizes, int n_in,
                              void* d_out, int out_size) {
    const float* z   = (const float*)d_in[0];   // [32,64,64,64]
    const float* emb = (const float*)d_in[1];   // [1024,64]
    float* out = (float*)d_out;                 // [32,64,64,64] + loss scalar

    znorm_kernel<<<NPTS / 256, 256>>>(z);
    enorm_kernel<<<KCODES / 256, 256>>>(emb);
    argmin_kernel<<<NPTS / 64, 256>>>(z, emb);
    gather_kernel<<<NPTS / 128, 256>>>(z, emb, out);
    loss_kernel<<<1, 256>>>(out, out_size);
}

// round 2
// speedup vs baseline: 1.0003x; 1.0003x over previous
#include <cuda_runtime.h>
#include <cstdint>

// Problem constants
#define BATCH 32
#define CDIM  64
#define HW    4096              // 64*64
#define NPTS  (BATCH * HW)      // 131072
#define KCODES 1024
#define ZQ_ELEMS (NPTS * CDIM)  // 8388608

// Scratch (device globals: allocation-free rule)
__device__ float  g_znorm[NPTS];
__device__ float  g_enorm[KCODES];
__device__ int    g_idx[NPTS];
__device__ double g_part[1024];

// ---------------------------------------------------------------------------
// Packed fp32x2 helpers (sm_103a: 2x fp32 FMA throughput, PTX-only)
// ---------------------------------------------------------------------------
__device__ __forceinline__ void fma2(unsigned long long& d,
                                     unsigned long long a,
                                     unsigned long long b) {
    asm("fma.rn.f32x2 %0, %1, %2, %0;" : "+l"(d) : "l"(a), "l"(b));
}
__device__ __forceinline__ unsigned long long dup_f32(float x) {
    unsigned long long r;
    unsigned int xi = __float_as_uint(x);
    asm("mov.b64 %0, {%1, %1};" : "=l"(r) : "r"(xi));
    return r;
}
__device__ __forceinline__ float lo_f32(unsigned long long v) {
    return __uint_as_float((unsigned int)(v & 0xFFFFFFFFull));
}
__device__ __forceinline__ float hi_f32(unsigned long long v) {
    return __uint_as_float((unsigned int)(v >> 32));
}

// ---------------------------------------------------------------------------
// Kernel 0a: per-point ||z||^2 (sequential fp32 sum over C, matching jnp.sum)
// ---------------------------------------------------------------------------
__global__ void znorm_kernel(const float* __restrict__ z) {
    int n = blockIdx.x * blockDim.x + threadIdx.x;   // 0..NPTS-1
    int b  = n >> 12;
    int hw = n & 4095;
    const float* p = z + (size_t)b * (CDIM * HW) + hw;
    float acc = 0.0f;
#pragma unroll
    for (int c = 0; c < CDIM; ++c) {
        float v = p[(size_t)c * HW];
        acc = __fadd_rn(acc, __fmul_rn(v, v));
    }
    g_znorm[n] = acc;
}

// ---------------------------------------------------------------------------
// Kernel 0b: per-code ||e||^2
// ---------------------------------------------------------------------------
__global__ void enorm_kernel(const float* __restrict__ emb) {
    int k = blockIdx.x * blockDim.x + threadIdx.x;   // 0..1023
    const float* p = emb + (size_t)k * CDIM;
    float acc = 0.0f;
#pragma unroll
    for (int c = 0; c < CDIM; ++c) {
        float v = p[c];
        acc = __fadd_rn(acc, __fmul_rn(v, v));
    }
    g_enorm[k] = acc;
}

// ---------------------------------------------------------------------------
// Kernel 1: fused distance-GEMM + argmin.
//   Block tile: 64 points x 128 codes per chunk, 8 chunks covering K=1024.
//   Thread tile: 4 points x 8 codes (4 f32x2 code-pairs) -> 16 fma.f32x2/iter.
//   d_k = fl( fl(znorm + enorm_k) - fl(2 * dot) ), argmin w/ lowest-k ties
//   via packed u64 key = (d_bits << 32) | k.
// ---------------------------------------------------------------------------
#define ESTRIDE 132  // 128 + 4 pad (floats per smem row)

__global__ __launch_bounds__(256) void argmin_kernel(
    const float* __restrict__ z, const float* __restrict__ emb) {
    __shared__ float e_s[CDIM * ESTRIDE];   // [c][k'] transposed, swizzled

    const int tid = threadIdx.x;
    const int tx = tid & 15;        // code group (16 x 8 codes = 128)
    const int ty = tid >> 4;        // point group (16 x 4 points = 64)

    const int m0  = blockIdx.x * 64;          // first point of block
    const int b   = m0 >> 12;
    const int hw0 = m0 & 4095;
    const float* zp = z + (size_t)b * (CDIM * HW) + hw0 + (ty << 2);

    // znorm for this thread's 4 points
    const float4 zn4 = *(const float4*)&g_znorm[m0 + (ty << 2)];
    const float znA[4] = {zn4.x, zn4.y, zn4.z, zn4.w};

    unsigned long long key[4];
#pragma unroll
    for (int i = 0; i < 4; ++i) key[i] = 0xFFFFFFFFFFFFFFFFull;

    for (int chunk = 0; chunk < 8; ++chunk) {
        const int kb = chunk << 7;   // 128 codes per chunk

        __syncthreads();
        // Cooperative transpose-load of emb chunk into e_s[c][k'^sig]
        {
            const int cg = tid & 15;        // c-group (4 floats)
            const int kk0 = tid >> 4;       // row within pass
            const int sig = (cg & 3) << 3;  // XOR swizzle on k' bits 3-4
#pragma unroll
            for (int p = 0; p < 8; ++p) {
                const int kk = (p << 4) + kk0;           // 0..127
                const float4 v = *(const float4*)&emb[(size_t)(kb + kk) * CDIM + (cg << 2)];
                const int col = kk ^ sig;
                e_s[((cg << 2) + 0) * ESTRIDE + col] = v.x;
                e_s[((cg << 2) + 1) * ESTRIDE + col] = v.y;
                e_s[((cg << 2) + 2) * ESTRIDE + col] = v.z;
                e_s[((cg << 2) + 3) * ESTRIDE + col] = v.w;
            }
        }
        __syncthreads();

        unsigned long long acc[16];
#pragma unroll
        for (int i = 0; i < 16; ++i) acc[i] = 0ull;

#pragma unroll 16
        for (int c = 0; c < CDIM; ++c) {
            const float4 zv = *(const float4*)(zp + (size_t)c * HW);
            unsigned long long za[4];
            za[0] = dup_f32(zv.x); za[1] = dup_f32(zv.y);
            za[2] = dup_f32(zv.z); za[3] = dup_f32(zv.w);

            const int sig = ((c >> 2) & 3) << 3;
            const int g0 = (tx << 3) ^ sig;              // 8-aligned
            const float* er = &e_s[c * ESTRIDE + g0];
            const ulonglong2 e01 = *(const ulonglong2*)er;        // codes tx*8+0..3
            const ulonglong2 e23 = *(const ulonglong2*)(er + 4);  // codes tx*8+4..7
            unsigned long long eb[4] = {e01.x, e01.y, e23.x, e23.y};

#pragma unroll
            for (int i = 0; i < 4; ++i)
#pragma unroll
                for (int n = 0; n < 4; ++n)
                    fma2(acc[i * 4 + n], za[i], eb[n]);
        }

        // Chunk epilogue: scores + running argmin
        const float4 en0 = *(const float4*)&g_enorm[kb + (tx << 3)];
        const float4 en1 = *(const float4*)&g_enorm[kb + (tx << 3) + 4];
        const float enA[8] = {en0.x, en0.y, en0.z, en0.w, en1.x, en1.y, en1.z, en1.w};
        const int kbase = kb + (tx << 3);

#pragma unroll
        for (int i = 0; i < 4; ++i) {
            const float zn = znA[i];
#pragma unroll
            for (int n = 0; n < 4; ++n) {
                const float alo = lo_f32(acc[i * 4 + n]);
                const float ahi = hi_f32(acc[i * 4 + n]);
                const float tlo = __fadd_rn(zn, enA[2 * n]);
                const float thi = __fadd_rn(zn, enA[2 * n + 1]);
                const float dlo = __fsub_rn(tlo, __fmul_rn(2.0f, alo));
                const float dhi = __fsub_rn(thi, __fmul_rn(2.0f, ahi));
                unsigned long long klo =
                    ((unsigned long long)__float_as_uint(dlo) << 32) |
                    (unsigned int)(kbase + 2 * n);
                unsigned long long khi =
                    ((unsigned long long)__float_as_uint(dhi) << 32) |
                    (unsigned int)(kbase + 2 * n + 1);
                if (klo < key[i]) key[i] = klo;
                if (khi < key[i]) key[i] = khi;
            }
        }
    }

    // Reduce over the 16 tx lanes sharing each point (xor stays within warp half)
#pragma unroll
    for (int i = 0; i < 4; ++i) {
#pragma unroll
        for (int off = 8; off >= 1; off >>= 1) {
            unsigned long long o = __shfl_xor_sync(0xFFFFFFFFu, key[i], off);
            if (o < key[i]) key[i] = o;
        }
    }
    if (tx == 0) {
#pragma unroll
        for (int i = 0; i < 4; ++i)
            g_idx[m0 + (ty << 2) + i] = (int)(key[i] & 0xFFFFFFFFull);
    }
}

// ---------------------------------------------------------------------------
// Kernel 2: gather z_q = emb[idx] into [B,C,H,W] layout + partial loss sums
// ---------------------------------------------------------------------------
__global__ __launch_bounds__(256) void gather_kernel(
    const float* __restrict__ z, const float* __restrict__ emb,
    float* __restrict__ out) {
    __shared__ int idx_s[128];
    __shared__ float es[128 * 68];
    __shared__ double red[256];

    const int tid = threadIdx.x;
    const int n0 = blockIdx.x * 128;
    const int b  = n0 >> 12;
    const int hw0 = n0 & 4095;

    if (tid < 128) idx_s[tid] = g_idx[n0 + tid];
    __syncthreads();

    // Stage 128 emb rows into smem (coalesced-by-row gather)
    {
        const int cg = tid & 15;
        const int i0 = tid >> 4;
#pragma unroll
        for (int p = 0; p < 8; ++p) {
            const int i = (p << 4) + i0;
            const float4 v = *(const float4*)&emb[(size_t)idx_s[i] * CDIM + (cg << 2)];
            *(float4*)&es[i * 68 + (cg << 2)] = v;
        }
    }
    __syncthreads();

    double acc = 0.0;
    const int m = tid & 127;
    const int chalf = tid >> 7;   // 0 or 1
#pragma unroll 8
    for (int p = 0; p < 32; ++p) {
        const int c = (p << 1) + chalf;
        const float e = es[m * 68 + c];
        const size_t off = (size_t)b * (CDIM * HW) + (size_t)c * HW + hw0 + m;
        const float zv = z[off];
        out[off] = e;
        const float d = __fsub_rn(e, zv);
        acc += (double)__fmul_rn(d, d);
    }

    red[tid] = acc;
    __syncthreads();
#pragma unroll
    for (int s = 128; s >= 1; s >>= 1) {
        if (tid < s) red[tid] += red[tid + s];
        __syncthreads();
    }
    if (tid == 0) g_part[blockIdx.x] = red[0];
}

// ---------------------------------------------------------------------------
// Kernel 3: deterministic final loss reduction.
//   loss = m + 0.5*m with m = fp32(mean((z_q - z)^2))
// ---------------------------------------------------------------------------
__global__ void loss_kernel(float* __restrict__ out, int out_size) {
    __shared__ double red[256];
    const int tid = threadIdx.x;
    double a = g_part[tid] + g_part[tid + 256] + g_part[tid + 512] + g_part[tid + 768];
    red[tid] = a;
    __syncthreads();
#pragma unroll
    for (int s = 128; s >= 1; s >>= 1) {
        if (tid < s) red[tid] += red[tid + s];
        __syncthreads();
    }
    if (tid == 0) {
        const double mean = red[0] / (double)ZQ_ELEMS;
        const float mf = (float)mean;
        out[out_size - 1] = __fadd_rn(mf, __fmul_rn(0.5f, mf));
    }
}

// ---------------------------------------------------------------------------
extern "C" void kernel_launch(void* const* d_in, const int* in_sizes, int n_in,
                              void* d_out, int out_size) {
    const float* z   = (const float*)d_in[0];   // [32,64,64,64]
    const float* emb = (const float*)d_in[1];   // [1024,64]
    float* out = (float*)d_out;                 // [32,64,64,64] + loss scalar

    znorm_kernel<<<NPTS / 256, 256>>>(z);
    enorm_kernel<<<KCODES / 256, 256>>>(emb);
    argmin_kernel<<<NPTS / 64, 256>>>(z, emb);
    gather_kernel<<<NPTS / 128, 256>>>(z, emb, out);
    loss_kernel<<<1, 256>>>(out, out_size);
}